// round 8
// baseline (speedup 1.0000x reference)
#include <cuda_runtime.h>
#include <cuda_bf16.h>
#include <math_constants.h>

// Problem constants
#define BB 16
#define TT 32
#define NP 8
#define NG 4
#define JJ 14
#define HH 256
#define BT (BB*TT)                    // 512
#define NPERM 1680
#define HEAT_N ((long long)BT*HH*HH)  // 33,554,432 floats = 8,388,608 float4/array

#define THREADS 256
#define NBLK 888                      // 148 SMs * 6 blocks -> single wave
#define DEPTH 4                       // slots; issue-ahead distance 3 < DEPTH (no WAR)
#define STAGE_F4 256                  // one float4 per thread per stage
#define CHUNK_STAGES 8
#define CHUNK_F4 (STAGE_F4*CHUNK_STAGES)   // 2048 float4 per chunk
#define NCHUNK 4096                   // 4096 * 2048 = 8,388,608 exactly

// cross-block scratch (device globals: allocation-free)
__device__ double g_mse[NBLK];
__device__ double g_off[BT];
__device__ double g_size[BT];
__device__ double g_pose[BT];
__device__ unsigned int g_chunk = 0;
__device__ unsigned int g_count = 0;

// ---------------- cp.async helpers ----------------
__device__ __forceinline__ void cp16(void* smem_dst, const void* gsrc) {
    unsigned s = (unsigned)__cvta_generic_to_shared(smem_dst);
    asm volatile("cp.async.cg.shared.global [%0], [%1], 16;" :: "r"(s), "l"(gsrc));
}
__device__ __forceinline__ void cp_commit() {
    asm volatile("cp.async.commit_group;");
}
__device__ __forceinline__ void cp_wait3() {
    asm volatile("cp.async.wait_group 3;");
}

// decode permutation index p (lexicographic, itertools.permutations(range(8),4))
__device__ __forceinline__ void decode_perm(int p, int rows[NG]) {
    int avail[NP] = {0,1,2,3,4,5,6,7};
    int r = p;
    int idx = r / 210; r -= idx * 210;
    rows[0] = avail[idx];
    #pragma unroll
    for (int k = 0; k < 7; k++) if (k >= idx) avail[k] = avail[k+1];
    idx = r / 30; r -= idx * 30;
    rows[1] = avail[idx];
    #pragma unroll
    for (int k = 0; k < 6; k++) if (k >= idx) avail[k] = avail[k+1];
    idx = r / 5; r -= idx * 5;
    rows[2] = avail[idx];
    #pragma unroll
    for (int k = 0; k < 5; k++) if (k >= idx) avail[k] = avail[k+1];
    rows[3] = avail[r];
}

// block-reduce a double with 256 threads; result valid on thread 0
__device__ __forceinline__ double block_reduce(double v, double* shm8) {
    #pragma unroll
    for (int off = 16; off > 0; off >>= 1)
        v += __shfl_down_sync(0xffffffffu, v, off);
    int lane = threadIdx.x & 31, wid = threadIdx.x >> 5;
    if (lane == 0) shm8[wid] = v;
    __syncthreads();
    double r = 0.0;
    if (wid == 0) {
        r = (lane < 8) ? shm8[lane] : 0.0;
        #pragma unroll
        for (int off = 4; off > 0; off >>= 1)
            r += __shfl_down_sync(0xffffffffu, r, off);
    }
    __syncthreads();
    return r;
}

struct MatchSmem {
    float Cb[NP][NG];
    float Cp[NP][NG];
    float pp[NP * JJ * 3];
    float gp[NG * JJ * 3];
    float rv[THREADS];
    int   ri[THREADS];
};
struct MseSmem {
    float4 h[DEPTH][THREADS];
    float4 g[DEPTH][THREADS];
};
union SmemU {
    MatchSmem match;
    MseSmem   mse;
};

__global__ __launch_bounds__(THREADS, 6)
void loss_kernel(const float4* __restrict__ heat,
                 const float4* __restrict__ gheat,
                 const float* __restrict__ hor_offset,
                 const float* __restrict__ hor_bsize,
                 const float* __restrict__ hor_center,
                 const float* __restrict__ scores,
                 const float* __restrict__ x_pose3d,
                 const float* __restrict__ gt_wh,
                 const float* __restrict__ gt_off,
                 const float* __restrict__ gt_center,
                 const float* __restrict__ gt_pose,
                 float* __restrict__ out) {
    __shared__ SmemU sm;
    __shared__ double shm8[8];
    __shared__ int s_chunk;
    const int t = threadIdx.x;
    const int b = blockIdx.x;

    // ---------------- per-(b,t) Hungarian matching (blocks 0..511) ----------------
    if (b < BT) {
        const int bt = b;
        const float* pc = hor_center + bt * NP * 2;
        const float* gc = gt_center  + bt * NG * 2;
        const float* sc = scores     + bt * NP;
        const float* po = hor_offset + bt * NP * 2;
        const float* go = gt_off     + bt * NG * 2;
        const float* ps = hor_bsize  + bt * NP * 4;
        const float* gs = gt_wh      + bt * NG * 4;
        const float* pp = x_pose3d   + bt * NP * JJ * 3;
        const float* gp = gt_pose    + bt * NG * JJ * 3;

        for (int i = t; i < NP * JJ * 3; i += THREADS) sm.match.pp[i] = pp[i];
        for (int i = t; i < NG * JJ * 3; i += THREADS) sm.match.gp[i] = gp[i];
        __syncthreads();

        if (t < NP * NG) {
            int i = t / NG, j = t % NG;
            float dx = pc[i*2]   - gc[j*2];
            float dy = pc[i*2+1] - gc[j*2+1];
            sm.match.Cb[i][j] = sqrtf(dx*dx + dy*dy) - sc[i];
            float acc = 0.0f;
            #pragma unroll
            for (int k = 0; k < JJ * 3; k++) {
                float d = sm.match.pp[i*JJ*3 + k] - sm.match.gp[j*JJ*3 + k];
                acc += d * d;
            }
            sm.match.Cp[i][j] = sqrtf(acc);
        }
        __syncthreads();

        float bvb = CUDART_INF_F, bvp = CUDART_INF_F;
        int bib = 0, bip = 0;
        for (int p = t; p < NPERM; p += THREADS) {
            int rows[NG];
            decode_perm(p, rows);
            float sb = sm.match.Cb[rows[0]][0] + sm.match.Cb[rows[1]][1]
                     + sm.match.Cb[rows[2]][2] + sm.match.Cb[rows[3]][3];
            float sp = sm.match.Cp[rows[0]][0] + sm.match.Cp[rows[1]][1]
                     + sm.match.Cp[rows[2]][2] + sm.match.Cp[rows[3]][3];
            if (sb < bvb) { bvb = sb; bib = p; }
            if (sp < bvp) { bvp = sp; bip = p; }
        }

        sm.match.rv[t] = bvb; sm.match.ri[t] = bib;
        __syncthreads();
        for (int s = THREADS >> 1; s > 0; s >>= 1) {
            if (t < s) {
                float vo = sm.match.rv[t + s]; int io = sm.match.ri[t + s];
                if (vo < sm.match.rv[t] || (vo == sm.match.rv[t] && io < sm.match.ri[t])) {
                    sm.match.rv[t] = vo; sm.match.ri[t] = io;
                }
            }
            __syncthreads();
        }
        int permb = sm.match.ri[0];
        __syncthreads();
        sm.match.rv[t] = bvp; sm.match.ri[t] = bip;
        __syncthreads();
        for (int s = THREADS >> 1; s > 0; s >>= 1) {
            if (t < s) {
                float vo = sm.match.rv[t + s]; int io = sm.match.ri[t + s];
                if (vo < sm.match.rv[t] || (vo == sm.match.rv[t] && io < sm.match.ri[t])) {
                    sm.match.rv[t] = vo; sm.match.ri[t] = io;
                }
            }
            __syncthreads();
        }
        int permp = sm.match.ri[0];

        if (t == 0) {
            int rb[NG], rp[NG];
            decode_perm(permb, rb);
            decode_perm(permp, rp);
            double off = 0.0, size = 0.0, pose = 0.0;
            #pragma unroll
            for (int j = 0; j < NG; j++) {
                int i = rb[j];
                float o = fabsf(po[i*2]   - go[j*2]) +
                          fabsf(po[i*2+1] - go[j*2+1]);
                off += (double)(o * 0.5f);
                float sz = fabsf(ps[i*4]   - gs[j*4]) +
                           fabsf(ps[i*4+1] - gs[j*4+1]) +
                           fabsf(ps[i*4+2] - gs[j*4+2]) +
                           fabsf(ps[i*4+3] - gs[j*4+3]);
                size += (double)(sz * 0.25f);
            }
            #pragma unroll
            for (int j = 0; j < NG; j++) {
                int i = rp[j];
                float acc = 0.0f;
                #pragma unroll
                for (int k = 0; k < JJ * 3; k++) {
                    float d = sm.match.pp[i*JJ*3 + k] - sm.match.gp[j*JJ*3 + k];
                    acc += d * d;
                }
                pose += (double)acc;
            }
            g_off[bt]  = off;
            g_size[bt] = size;
            g_pose[bt] = pose;
        }
        __syncthreads();   // smem union: matching done before MSE reuses it
    }

    // ---- heatmap MSE: continuous cp.async pipeline + lookahead chunk stealing ----
    float a0 = 0.f, a1 = 0.f, a2 = 0.f, a3 = 0.f;

    if (t == 0) s_chunk = (int)atomicAdd(&g_chunk, 1u);
    __syncthreads();
    int cur = s_chunk;
    __syncthreads();   // protect s_chunk before next write

    if (cur < NCHUNK) {
        const float4* hc = heat  + (unsigned)cur * CHUNK_F4 + t;
        const float4* gc = gheat + (unsigned)cur * CHUNK_F4 + t;
        // prologue: stages 0..2 -> slots 0..2
        #pragma unroll
        for (int s = 0; s < 3; s++) {
            cp16(&sm.mse.h[s][t], hc + s * STAGE_F4);
            cp16(&sm.mse.g[s][t], gc + s * STAGE_F4);
            cp_commit();
        }
        int islot = 3, rslot = 0;
        for (;;) {
            // grab next chunk early; its first 3 stages are issued in this
            // chunk's tail iterations so the pipeline never drains.
            if (t == 0) s_chunk = (int)atomicAdd(&g_chunk, 1u);
            __syncthreads();
            int nxt = s_chunk;
            __syncthreads();   // reads done before next write
            bool have_nxt = nxt < NCHUNK;
            const float4* hn = heat  + (unsigned)nxt * CHUNK_F4 + t;
            const float4* gn = gheat + (unsigned)nxt * CHUNK_F4 + t;

            #pragma unroll
            for (int s = 0; s < CHUNK_STAGES; s++) {
                int is = s + 3;
                if (is < CHUNK_STAGES) {
                    cp16(&sm.mse.h[islot][t], hc + is * STAGE_F4);
                    cp16(&sm.mse.g[islot][t], gc + is * STAGE_F4);
                } else if (have_nxt) {
                    cp16(&sm.mse.h[islot][t], hn + (is - CHUNK_STAGES) * STAGE_F4);
                    cp16(&sm.mse.g[islot][t], gn + (is - CHUNK_STAGES) * STAGE_F4);
                }
                cp_commit();
                cp_wait3();
                // read slot: its group is complete; issue slot != read slot (DEPTH=4)
                float4 x = sm.mse.h[rslot][t];
                float4 y = sm.mse.g[rslot][t];
                float d0 = x.x - y.x, d1 = x.y - y.y;
                float d2 = x.z - y.z, d3 = x.w - y.w;
                a0 = fmaf(d0, d0, a0);
                a1 = fmaf(d1, d1, a1);
                a2 = fmaf(d2, d2, a2);
                a3 = fmaf(d3, d3, a3);
                islot = (islot + 1) & 3;
                rslot = (rslot + 1) & 3;
            }
            if (!have_nxt) break;
            hc = hn; gc = gn;
        }
    }
    asm volatile("cp.async.wait_group 0;");

    double s = (double)((a0 + a1) + (a2 + a3));
    double bs = block_reduce(s, shm8);
    if (t == 0) g_mse[b] = bs;

    // ---------------- last-block final reduction ----------------
    __shared__ int s_last;
    __threadfence();
    if (t == 0) {
        unsigned int v = atomicAdd(&g_count, 1u);
        s_last = (v == NBLK - 1) ? 1 : 0;
    }
    __syncthreads();
    if (!s_last) return;

    double c = 0.0, o = 0.0, sz = 0.0, pz = 0.0;
    for (int i = t; i < NBLK; i += THREADS) c += __ldcg(&g_mse[i]);
    for (int i = t; i < BT; i += THREADS) {
        o  += __ldcg(&g_off[i]);
        sz += __ldcg(&g_size[i]);
        pz += __ldcg(&g_pose[i]);
    }
    c  = block_reduce(c,  shm8);
    o  = block_reduce(o,  shm8);
    sz = block_reduce(sz, shm8);
    pz = block_reduce(pz, shm8);
    if (t == 0) {
        double center = c / (double)HEAT_N;
        double detection = center + o / (double)BT + sz / (double)BT;
        double pose = pz / (double)((long long)BT * NP * JJ);
        out[0] = (float)(detection + pose);   // GAMMA = 1.0
        g_count = 0;                          // reset for next graph replay
        g_chunk = 0;
    }
}

extern "C" void kernel_launch(void* const* d_in, const int* in_sizes, int n_in,
                              void* d_out, int out_size) {
    const float* hor_heatmap = (const float*)d_in[0];
    const float* hor_offset  = (const float*)d_in[1];
    const float* hor_bsize   = (const float*)d_in[2];
    const float* hor_center  = (const float*)d_in[3];
    const float* scores      = (const float*)d_in[4];
    const float* x_pose3d    = (const float*)d_in[5];
    const float* gt_heatmap  = (const float*)d_in[6];
    const float* gt_wh       = (const float*)d_in[7];
    const float* gt_off      = (const float*)d_in[8];
    const float* gt_center   = (const float*)d_in[9];
    const float* gt_pose     = (const float*)d_in[10];
    float* out = (float*)d_out;

    loss_kernel<<<NBLK, THREADS>>>(
        (const float4*)hor_heatmap, (const float4*)gt_heatmap,
        hor_offset, hor_bsize, hor_center, scores, x_pose3d,
        gt_wh, gt_off, gt_center, gt_pose, out);
}

// round 10
// speedup vs baseline: 1.0450x; 1.0450x over previous
#include <cuda_runtime.h>
#include <cuda_bf16.h>
#include <math_constants.h>
#include <cstdint>

// Problem constants
#define BB 16
#define TT 32
#define NP 8
#define NG 4
#define JJ 14
#define HH 256
#define BT (BB*TT)                    // 512
#define NPERM 1680
#define HEAT_N ((long long)BT*HH*HH)  // 33,554,432 floats = 8,388,608 float4/array

#define THREADS 256
#define NBLK 888                      // 148 SMs * 6 blocks -> single wave
#define NSLOT 4
#define STAGE_F4 256                  // float4 per array per stage (4 KB)
#define STAGES_PER_CHUNK 4
#define CHUNK_F4 (STAGE_F4*STAGES_PER_CHUNK)   // 1024 float4
#define NCHUNK 8192                   // 8192*1024 = 8,388,608 exactly
#define STAGE_BYTES (STAGE_F4*16)     // 4096 per array
#define TX_BYTES (2*STAGE_BYTES)      // 8192 per stage (both arrays)

// cross-block scratch (device globals: allocation-free)
__device__ double g_mse[NBLK];
__device__ double g_off[BT];
__device__ double g_size[BT];
__device__ double g_pose[BT];
__device__ unsigned int g_chunk = 0;
__device__ unsigned int g_count = 0;

// ---------------- mbarrier / bulk-async helpers ----------------
__device__ __forceinline__ uint32_t s2u(const void* p) {
    return (uint32_t)__cvta_generic_to_shared(p);
}
__device__ __forceinline__ void mbar_init(uint32_t a, uint32_t cnt) {
    asm volatile("mbarrier.init.shared::cta.b64 [%0], %1;" :: "r"(a), "r"(cnt) : "memory");
}
__device__ __forceinline__ void fence_proxy_async_cta() {
    asm volatile("fence.proxy.async.shared::cta;" ::: "memory");
}
__device__ __forceinline__ void mbar_expect_tx(uint32_t a, uint32_t bytes) {
    asm volatile("mbarrier.arrive.expect_tx.shared::cta.b64 _, [%0], %1;"
                 :: "r"(a), "r"(bytes) : "memory");
}
__device__ __forceinline__ void mbar_wait(uint32_t a, uint32_t phase) {
    asm volatile(
        "{\n\t.reg .pred P;\n\t"
        "W%=:\n\t"
        "mbarrier.try_wait.parity.acquire.cta.shared::cta.b64 P, [%0], %1, 0x989680;\n\t"
        "@P bra D%=;\n\t"
        "bra W%=;\n\t"
        "D%=:\n\t}"
        :: "r"(a), "r"(phase) : "memory");
}
__device__ __forceinline__ void bulk_g2s(uint32_t sdst, const void* gsrc,
                                         uint32_t bytes, uint32_t mbar) {
    asm volatile(
        "cp.async.bulk.shared::cta.global.mbarrier::complete_tx::bytes [%0], [%1], %2, [%3];"
        :: "r"(sdst), "l"(gsrc), "r"(bytes), "r"(mbar) : "memory");
}

// decode permutation index p (lexicographic, itertools.permutations(range(8),4))
__device__ __forceinline__ void decode_perm(int p, int rows[NG]) {
    int avail[NP] = {0,1,2,3,4,5,6,7};
    int r = p;
    int idx = r / 210; r -= idx * 210;
    rows[0] = avail[idx];
    #pragma unroll
    for (int k = 0; k < 7; k++) if (k >= idx) avail[k] = avail[k+1];
    idx = r / 30; r -= idx * 30;
    rows[1] = avail[idx];
    #pragma unroll
    for (int k = 0; k < 6; k++) if (k >= idx) avail[k] = avail[k+1];
    idx = r / 5; r -= idx * 5;
    rows[2] = avail[idx];
    #pragma unroll
    for (int k = 0; k < 5; k++) if (k >= idx) avail[k] = avail[k+1];
    rows[3] = avail[r];
}

// block-reduce a double with 256 threads; result valid on thread 0
__device__ __forceinline__ double block_reduce(double v, double* shm8) {
    #pragma unroll
    for (int off = 16; off > 0; off >>= 1)
        v += __shfl_down_sync(0xffffffffu, v, off);
    int lane = threadIdx.x & 31, wid = threadIdx.x >> 5;
    if (lane == 0) shm8[wid] = v;
    __syncthreads();
    double r = 0.0;
    if (wid == 0) {
        r = (lane < 8) ? shm8[lane] : 0.0;
        #pragma unroll
        for (int off = 4; off > 0; off >>= 1)
            r += __shfl_down_sync(0xffffffffu, r, off);
    }
    __syncthreads();
    return r;
}

struct MatchSmem {
    float Cb[NP][NG];
    float Cp[NP][NG];
    float pp[NP * JJ * 3];
    float gp[NG * JJ * 3];
    float rv[THREADS];
    int   ri[THREADS];
};

__global__ __launch_bounds__(THREADS, 6)
void loss_kernel(const float4* __restrict__ heat,
                 const float4* __restrict__ gheat,
                 const float* __restrict__ hor_offset,
                 const float* __restrict__ hor_bsize,
                 const float* __restrict__ hor_center,
                 const float* __restrict__ scores,
                 const float* __restrict__ x_pose3d,
                 const float* __restrict__ gt_wh,
                 const float* __restrict__ gt_off,
                 const float* __restrict__ gt_center,
                 const float* __restrict__ gt_pose,
                 float* __restrict__ out) {
    __shared__ __align__(16) float4 hbuf[NSLOT][STAGE_F4];
    __shared__ __align__(16) float4 gbuf[NSLOT][STAGE_F4];
    __shared__ __align__(8) uint64_t mbar_s[NSLOT];
    __shared__ MatchSmem sm;
    __shared__ double shm8[8];
    __shared__ int s_chunk;
    const int t = threadIdx.x;
    const int b = blockIdx.x;

    if (t < NSLOT) mbar_init(s2u(&mbar_s[t]), 1);
    // Make the generic-proxy mbarrier init visible to the async proxy BEFORE
    // any cp.async.bulk targets these barriers. Missing this fence can hang
    // the parity wait (async proxy sees uninitialized barrier state).
    fence_proxy_async_cta();
    __syncthreads();

    // ---------------- per-(b,t) Hungarian matching (blocks 0..511) ----------------
    if (b < BT) {
        const int bt = b;
        const float* pc = hor_center + bt * NP * 2;
        const float* gc = gt_center  + bt * NG * 2;
        const float* sc = scores     + bt * NP;
        const float* po = hor_offset + bt * NP * 2;
        const float* go = gt_off     + bt * NG * 2;
        const float* ps = hor_bsize  + bt * NP * 4;
        const float* gs = gt_wh      + bt * NG * 4;
        const float* pp = x_pose3d   + bt * NP * JJ * 3;
        const float* gp = gt_pose    + bt * NG * JJ * 3;

        for (int i = t; i < NP * JJ * 3; i += THREADS) sm.pp[i] = pp[i];
        for (int i = t; i < NG * JJ * 3; i += THREADS) sm.gp[i] = gp[i];
        __syncthreads();

        if (t < NP * NG) {
            int i = t / NG, j = t % NG;
            float dx = pc[i*2]   - gc[j*2];
            float dy = pc[i*2+1] - gc[j*2+1];
            sm.Cb[i][j] = sqrtf(dx*dx + dy*dy) - sc[i];
            float acc = 0.0f;
            #pragma unroll
            for (int k = 0; k < JJ * 3; k++) {
                float d = sm.pp[i*JJ*3 + k] - sm.gp[j*JJ*3 + k];
                acc += d * d;
            }
            sm.Cp[i][j] = sqrtf(acc);
        }
        __syncthreads();

        float bvb = CUDART_INF_F, bvp = CUDART_INF_F;
        int bib = 0, bip = 0;
        for (int p = t; p < NPERM; p += THREADS) {
            int rows[NG];
            decode_perm(p, rows);
            float sb = sm.Cb[rows[0]][0] + sm.Cb[rows[1]][1]
                     + sm.Cb[rows[2]][2] + sm.Cb[rows[3]][3];
            float sp = sm.Cp[rows[0]][0] + sm.Cp[rows[1]][1]
                     + sm.Cp[rows[2]][2] + sm.Cp[rows[3]][3];
            if (sb < bvb) { bvb = sb; bib = p; }
            if (sp < bvp) { bvp = sp; bip = p; }
        }

        sm.rv[t] = bvb; sm.ri[t] = bib;
        __syncthreads();
        for (int s = THREADS >> 1; s > 0; s >>= 1) {
            if (t < s) {
                float vo = sm.rv[t + s]; int io = sm.ri[t + s];
                if (vo < sm.rv[t] || (vo == sm.rv[t] && io < sm.ri[t])) {
                    sm.rv[t] = vo; sm.ri[t] = io;
                }
            }
            __syncthreads();
        }
        int permb = sm.ri[0];
        __syncthreads();
        sm.rv[t] = bvp; sm.ri[t] = bip;
        __syncthreads();
        for (int s = THREADS >> 1; s > 0; s >>= 1) {
            if (t < s) {
                float vo = sm.rv[t + s]; int io = sm.ri[t + s];
                if (vo < sm.rv[t] || (vo == sm.rv[t] && io < sm.ri[t])) {
                    sm.rv[t] = vo; sm.ri[t] = io;
                }
            }
            __syncthreads();
        }
        int permp = sm.ri[0];

        if (t == 0) {
            int rb[NG], rp[NG];
            decode_perm(permb, rb);
            decode_perm(permp, rp);
            double off = 0.0, size = 0.0, pose = 0.0;
            #pragma unroll
            for (int j = 0; j < NG; j++) {
                int i = rb[j];
                float o = fabsf(po[i*2]   - go[j*2]) +
                          fabsf(po[i*2+1] - go[j*2+1]);
                off += (double)(o * 0.5f);
                float sz = fabsf(ps[i*4]   - gs[j*4]) +
                           fabsf(ps[i*4+1] - gs[j*4+1]) +
                           fabsf(ps[i*4+2] - gs[j*4+2]) +
                           fabsf(ps[i*4+3] - gs[j*4+3]);
                size += (double)(sz * 0.25f);
            }
            #pragma unroll
            for (int j = 0; j < NG; j++) {
                int i = rp[j];
                float acc = 0.0f;
                #pragma unroll
                for (int k = 0; k < JJ * 3; k++) {
                    float d = sm.pp[i*JJ*3 + k] - sm.gp[j*JJ*3 + k];
                    acc += d * d;
                }
                pose += (double)acc;
            }
            g_off[bt]  = off;
            g_size[bt] = size;
            g_pose[bt] = pose;
        }
        __syncthreads();
    }

    // ---- heatmap MSE: bulk-async (UBLKCP) ring + lookahead chunk stealing ----
    // All slot indices are compile-time. Producer = thread 0. Per-stage
    // __syncthreads recycles slots (read -> sync -> reissue).
    float a0 = 0.f, a1 = 0.f, a2 = 0.f, a3 = 0.f;

    if (t == 0) s_chunk = (int)atomicAdd(&g_chunk, 1u);
    __syncthreads();
    int cur = s_chunk;
    __syncthreads();

    int ph[NSLOT] = {0, 0, 0, 0};

    if (cur < NCHUNK) {
        const char* hc = (const char*)(heat  + (unsigned)cur * CHUNK_F4);
        const char* gc = (const char*)(gheat + (unsigned)cur * CHUNK_F4);
        // prologue: stages 0..2 of cur -> slots 0..2
        if (t == 0) {
            #pragma unroll
            for (int s = 0; s < 3; s++) {
                uint32_t mb = s2u(&mbar_s[s]);
                mbar_expect_tx(mb, TX_BYTES);
                bulk_g2s(s2u(&hbuf[s][0]), hc + s * STAGE_BYTES, STAGE_BYTES, mb);
                bulk_g2s(s2u(&gbuf[s][0]), gc + s * STAGE_BYTES, STAGE_BYTES, mb);
            }
        }
        for (;;) {
            // lookahead steal: only t0 needs the id for issuing; everyone
            // reads the loop-exit decision after stage-0's syncthreads.
            if (t == 0) s_chunk = (int)atomicAdd(&g_chunk, 1u);
            const char* hn = nullptr; const char* gn = nullptr;
            bool have_nxt = false;

            #pragma unroll
            for (int s = 0; s < STAGES_PER_CHUNK; s++) {
                const int islot = (s + 3) & 3;     // compile-time
                const int rslot = s & 3;           // compile-time
                if (t == 0) {
                    if (s + 3 < STAGES_PER_CHUNK) {
                        uint32_t mb = s2u(&mbar_s[islot]);
                        mbar_expect_tx(mb, TX_BYTES);
                        bulk_g2s(s2u(&hbuf[islot][0]), hc + (s + 3) * STAGE_BYTES, STAGE_BYTES, mb);
                        bulk_g2s(s2u(&gbuf[islot][0]), gc + (s + 3) * STAGE_BYTES, STAGE_BYTES, mb);
                    } else if (have_nxt) {
                        int ns = s + 3 - STAGES_PER_CHUNK;
                        uint32_t mb = s2u(&mbar_s[islot]);
                        mbar_expect_tx(mb, TX_BYTES);
                        bulk_g2s(s2u(&hbuf[islot][0]), hn + ns * STAGE_BYTES, STAGE_BYTES, mb);
                        bulk_g2s(s2u(&gbuf[islot][0]), gn + ns * STAGE_BYTES, STAGE_BYTES, mb);
                    }
                }
                mbar_wait(s2u(&mbar_s[rslot]), (uint32_t)ph[rslot]);
                ph[rslot] ^= 1;
                float4 x = hbuf[rslot][t];
                float4 y = gbuf[rslot][t];
                float d0 = x.x - y.x, d1 = x.y - y.y;
                float d2 = x.z - y.z, d3 = x.w - y.w;
                a0 = fmaf(d0, d0, a0);
                a1 = fmaf(d1, d1, a1);
                a2 = fmaf(d2, d2, a2);
                a3 = fmaf(d3, d3, a3);
                __syncthreads();   // all reads of rslot done -> slot reusable
                if (s == 0) {
                    int nxt = s_chunk;             // visible after the sync
                    have_nxt = nxt < NCHUNK;
                    hn = (const char*)(heat  + (unsigned)nxt * CHUNK_F4);
                    gn = (const char*)(gheat + (unsigned)nxt * CHUNK_F4);
                }
            }
            if (!have_nxt) break;
            hc = hn; gc = gn;
        }
    }

    double s = (double)((a0 + a1) + (a2 + a3));
    double bs = block_reduce(s, shm8);
    if (t == 0) g_mse[b] = bs;

    // ---------------- last-block final reduction ----------------
    __shared__ int s_last;
    __threadfence();
    if (t == 0) {
        unsigned int v = atomicAdd(&g_count, 1u);
        s_last = (v == NBLK - 1) ? 1 : 0;
    }
    __syncthreads();
    if (!s_last) return;

    double c = 0.0, o = 0.0, sz = 0.0, pz = 0.0;
    for (int i = t; i < NBLK; i += THREADS) c += __ldcg(&g_mse[i]);
    for (int i = t; i < BT; i += THREADS) {
        o  += __ldcg(&g_off[i]);
        sz += __ldcg(&g_size[i]);
        pz += __ldcg(&g_pose[i]);
    }
    c  = block_reduce(c,  shm8);
    o  = block_reduce(o,  shm8);
    sz = block_reduce(sz, shm8);
    pz = block_reduce(pz, shm8);
    if (t == 0) {
        double center = c / (double)HEAT_N;
        double detection = center + o / (double)BT + sz / (double)BT;
        double pose = pz / (double)((long long)BT * NP * JJ);
        out[0] = (float)(detection + pose);   // GAMMA = 1.0
        g_count = 0;                          // reset for next graph replay
        g_chunk = 0;
    }
}

extern "C" void kernel_launch(void* const* d_in, const int* in_sizes, int n_in,
                              void* d_out, int out_size) {
    const float* hor_heatmap = (const float*)d_in[0];
    const float* hor_offset  = (const float*)d_in[1];
    const float* hor_bsize   = (const float*)d_in[2];
    const float* hor_center  = (const float*)d_in[3];
    const float* scores      = (const float*)d_in[4];
    const float* x_pose3d    = (const float*)d_in[5];
    const float* gt_heatmap  = (const float*)d_in[6];
    const float* gt_wh       = (const float*)d_in[7];
    const float* gt_off      = (const float*)d_in[8];
    const float* gt_center   = (const float*)d_in[9];
    const float* gt_pose     = (const float*)d_in[10];
    float* out = (float*)d_out;

    loss_kernel<<<NBLK, THREADS>>>(
        (const float4*)hor_heatmap, (const float4*)gt_heatmap,
        hor_offset, hor_bsize, hor_center, scores, x_pose3d,
        gt_wh, gt_off, gt_center, gt_pose, out);
}